// round 3
// baseline (speedup 1.0000x reference)
#include <cuda_runtime.h>
#include <cstddef>

// Problem constants (fixed by the dataset)
#define DD 16     // ds_dim
#define NN 32     // number of systems
#define HH 128    // gating hidden width
#define THREADS 256
#define RPT 2     // rows per thread

typedef unsigned long long ull;

// ---- f32x2 packed-math helpers (sm_103a) ----
__device__ __forceinline__ ull pack2(float lo, float hi) {
    ull r; asm("mov.b64 %0, {%1,%2};" : "=l"(r) : "f"(lo), "f"(hi)); return r;
}
__device__ __forceinline__ ull dup2(float v) { return pack2(v, v); }
__device__ __forceinline__ void unpack2(ull v, float& lo, float& hi) {
    asm("mov.b64 {%0,%1}, %2;" : "=f"(lo), "=f"(hi) : "l"(v));
}
__device__ __forceinline__ ull fma2(ull a, ull b, ull c) {
    ull d; asm("fma.rn.f32x2 %0, %1, %2, %3;" : "=l"(d) : "l"(a), "l"(b), "l"(c));
    return d;
}
__device__ __forceinline__ ull add2(ull a, ull b) {
    ull d; asm("add.rn.f32x2 %0, %1, %2;" : "=l"(d) : "l"(a), "l"(b)); return d;
}

// Dynamic smem layout (floats):
//   sW1  [H*D]        NEGATED W1: sW1[j*16+d] = -W1[j][d]
//   sW2t [H*N]        transposed: sW2t[j*N + n] = W2[n*H + j]
//   sA   [N*D*D]      transposed A: sA[n*256 + d*16 + k] = (B+C)[n][k][d]
//   sb1p [H]          b1'[j] = b1[j] + sum_d W1[j][d]*xt[d]
//   sb2  [N]
//   sxt  [D]
//   swb  [N*RPT*THREADS]  per-thread normalized softmax weights
#define W_FLOATS (HH*DD + HH*NN + NN*DD*DD + HH + NN + DD)
#define SMEM_FLOATS (W_FLOATS + NN*RPT*THREADS)

__global__ __launch_bounds__(THREADS, 2)
void fused_gated_ds_kernel(
    const float* __restrict__ x_cur,
    const float* __restrict__ W1,
    const float* __restrict__ b1,
    const float* __restrict__ W2,
    const float* __restrict__ b2,
    const float* __restrict__ Bm,
    const float* __restrict__ Cm,
    const float* __restrict__ xt,
    float* __restrict__ out,
    int Btot)
{
    extern __shared__ float smem[];
    float* sW1  = smem;                    // 2048
    float* sW2t = sW1  + HH*DD;            // 4096
    float* sA   = sW2t + HH*NN;            // 8192
    float* sb1p = sA   + NN*DD*DD;         // 128
    float* sb2  = sb1p + HH;               // 32
    float* sxt  = sb2  + NN;               // 16
    float* swb  = smem + W_FLOATS;         // 16384

    const int tid = threadIdx.x;

    // ---- stage weights ----
    for (int i = tid; i < HH*DD; i += THREADS) sW1[i] = -W1[i];
    for (int i = tid; i < HH*NN; i += THREADS) {
        int j = i / NN, n = i % NN;
        sW2t[i] = W2[n*HH + j];
    }
    for (int i = tid; i < NN*DD*DD; i += THREADS) {
        int n = i / (DD*DD);
        int r = i % (DD*DD);
        int d = r / DD, k = r % DD;
        int src = n*DD*DD + k*DD + d;      // A[n][k][d] -> sA[n][d][k]
        sA[i] = Bm[src] + Cm[src];
    }
    if (tid < NN) sb2[tid] = b2[tid];
    if (tid < DD) sxt[tid] = xt[tid];
    __syncthreads();

    // b1'[j] = b1[j] + sum_d W1[j][d]*xt[d]  (sW1 holds -W1)
    if (tid < HH) {
        float s = b1[tid];
        #pragma unroll
        for (int d = 0; d < DD; d++) s -= sW1[tid*DD + d] * sxt[d];
        sb1p[tid] = s;
    }
    __syncthreads();

    const int base = blockIdx.x * (THREADS * RPT);
    const int r0 = base + tid;
    const int r1 = base + THREADS + tid;
    if (r0 >= Btot) return;
    const bool act1 = (r1 < Btot);

    const ull MINUS1 = dup2(-1.0f);

    // ---- diff = x_target - x, computed packed straight from the load ----
    ull diffp[RPT][8];
    {
        ull sxtp[8];
        const ulonglong2* xtp = reinterpret_cast<const ulonglong2*>(sxt);
        #pragma unroll
        for (int q = 0; q < 4; q++) { ulonglong2 v = xtp[q]; sxtp[2*q] = v.x; sxtp[2*q+1] = v.y; }

        const ulonglong2* xg = reinterpret_cast<const ulonglong2*>(x_cur + (size_t)r0 * DD);
        #pragma unroll
        for (int q = 0; q < 4; q++) {
            ulonglong2 v = xg[q];
            diffp[0][2*q]   = fma2(v.x, MINUS1, sxtp[2*q]);
            diffp[0][2*q+1] = fma2(v.y, MINUS1, sxtp[2*q+1]);
        }
        if (act1) {
            const ulonglong2* xg1 = reinterpret_cast<const ulonglong2*>(x_cur + (size_t)r1 * DD);
            #pragma unroll
            for (int q = 0; q < 4; q++) {
                ulonglong2 v = xg1[q];
                diffp[1][2*q]   = fma2(v.x, MINUS1, sxtp[2*q]);
                diffp[1][2*q+1] = fma2(v.y, MINUS1, sxtp[2*q+1]);
            }
        } else {
            #pragma unroll
            for (int i = 0; i < 8; i++) diffp[1][i] = 0ULL;
        }
    }

    // ---- logits, packed over n ----
    ull Lp[RPT][16];
    {
        const ulonglong2* b2p = reinterpret_cast<const ulonglong2*>(sb2);
        #pragma unroll
        for (int q = 0; q < 8; q++) {
            ulonglong2 v = b2p[q];
            Lp[0][2*q]   = v.x; Lp[0][2*q+1] = v.y;
            Lp[1][2*q]   = v.x; Lp[1][2*q+1] = v.y;
        }
    }

    // ---- fused GEMM1 (relu, bias-folded) + GEMM2, streaming over j ----
    #pragma unroll 2
    for (int j = 0; j < HH; j++) {
        const ulonglong2* w1p = reinterpret_cast<const ulonglong2*>(sW1 + j*DD);
        ulonglong2 wA = w1p[0], wB = w1p[1];
        const float bj = sb1p[j];
        ull hd[RPT];
        #pragma unroll
        for (int r = 0; r < RPT; r++) {
            ull s0 = fma2(wA.x, diffp[r][0], 0ULL);
            ull s1 = fma2(wA.y, diffp[r][1], 0ULL);
            s0 = fma2(wB.x, diffp[r][2], s0);
            s1 = fma2(wB.y, diffp[r][3], s1);
            ulonglong2 wC = w1p[2], wD = w1p[3];
            s0 = fma2(wC.x, diffp[r][4], s0);
            s1 = fma2(wC.y, diffp[r][5], s1);
            s0 = fma2(wD.x, diffp[r][6], s0);
            s1 = fma2(wD.y, diffp[r][7], s1);
            ull s = add2(s0, s1);
            float lo, hi; unpack2(s, lo, hi);
            float hj = fmaxf(lo + hi + bj, 0.0f);
            hd[r] = dup2(hj);
        }
        const ulonglong2* w2p = reinterpret_cast<const ulonglong2*>(sW2t + j*NN);
        #pragma unroll
        for (int q = 0; q < 8; q++) {
            ulonglong2 wv = w2p[q];
            #pragma unroll
            for (int r = 0; r < RPT; r++) {
                Lp[r][2*q]   = fma2(wv.x, hd[r], Lp[r][2*q]);
                Lp[r][2*q+1] = fma2(wv.y, hd[r], Lp[r][2*q+1]);
            }
        }
    }

    // ---- softmax per row; store pre-normalized weights to SMEM ----
    #pragma unroll
    for (int r = 0; r < RPT; r++) {
        float ev[NN];
        #pragma unroll
        for (int i = 0; i < 16; i++) unpack2(Lp[r][i], ev[2*i], ev[2*i+1]);
        float m = ev[0];
        #pragma unroll
        for (int n = 1; n < NN; n++) m = fmaxf(m, ev[n]);
        float s = 0.0f;
        #pragma unroll
        for (int n = 0; n < NN; n++) { ev[n] = __expf(ev[n] - m); s += ev[n]; }
        const float inv = 1.0f / s;
        #pragma unroll
        for (int n = 0; n < NN; n++) swb[(n*RPT + r)*THREADS + tid] = ev[n] * inv;
    }

    // ---- unpack diff to scalars (Lp is dead; regs recycled) ----
    float diffs[RPT][DD];
    #pragma unroll
    for (int r = 0; r < RPT; r++) {
        #pragma unroll
        for (int q = 0; q < 8; q++)
            unpack2(diffp[r][q], diffs[r][2*q], diffs[r][2*q+1]);
    }

    // ---- epilogue: out[k] = sum_n sum_d A[n][d][k] * (w_n*diff[d]) ----
    ull outp[RPT][8];
    #pragma unroll
    for (int r = 0; r < RPT; r++)
        #pragma unroll
        for (int q = 0; q < 8; q++) outp[r][q] = 0ULL;

    #pragma unroll 1
    for (int n = 0; n < NN; n++) {
        const ulonglong2* ap = reinterpret_cast<const ulonglong2*>(sA + n*DD*DD);
        float wn[RPT];
        #pragma unroll
        for (int r = 0; r < RPT; r++) wn[r] = swb[(n*RPT + r)*THREADS + tid];

        #pragma unroll
        for (int d = 0; d < DD; d++) {
            ulonglong2 aA = ap[4*d + 0];
            ulonglong2 aB = ap[4*d + 1];
            ulonglong2 aC = ap[4*d + 2];
            ulonglong2 aD = ap[4*d + 3];
            #pragma unroll
            for (int r = 0; r < RPT; r++) {
                const ull ddv = dup2(wn[r] * diffs[r][d]);
                outp[r][0] = fma2(aA.x, ddv, outp[r][0]);
                outp[r][1] = fma2(aA.y, ddv, outp[r][1]);
                outp[r][2] = fma2(aB.x, ddv, outp[r][2]);
                outp[r][3] = fma2(aB.y, ddv, outp[r][3]);
                outp[r][4] = fma2(aC.x, ddv, outp[r][4]);
                outp[r][5] = fma2(aC.y, ddv, outp[r][5]);
                outp[r][6] = fma2(aD.x, ddv, outp[r][6]);
                outp[r][7] = fma2(aD.y, ddv, outp[r][7]);
            }
        }
    }

    // ---- store (weights already normalized) ----
    {
        float4* o = reinterpret_cast<float4*>(out + (size_t)r0 * DD);
        #pragma unroll
        for (int q = 0; q < 4; q++) {
            float a, b, c, d;
            unpack2(outp[0][2*q], a, b);
            unpack2(outp[0][2*q+1], c, d);
            o[q] = make_float4(a, b, c, d);
        }
    }
    if (act1) {
        float4* o = reinterpret_cast<float4*>(out + (size_t)r1 * DD);
        #pragma unroll
        for (int q = 0; q < 4; q++) {
            float a, b, c, d;
            unpack2(outp[1][2*q], a, b);
            unpack2(outp[1][2*q+1], c, d);
            o[q] = make_float4(a, b, c, d);
        }
    }
}

extern "C" void kernel_launch(void* const* d_in, const int* in_sizes, int n_in,
                              void* d_out, int out_size)
{
    const float* x_cur = (const float*)d_in[0];
    const float* W1    = (const float*)d_in[1];
    const float* b1    = (const float*)d_in[2];
    const float* W2    = (const float*)d_in[3];
    const float* b2    = (const float*)d_in[4];
    const float* Bm    = (const float*)d_in[5];
    const float* Cm    = (const float*)d_in[6];
    const float* xt    = (const float*)d_in[7];
    float* out = (float*)d_out;

    const int Btot = in_sizes[0] / DD;
    const size_t smem_bytes = (size_t)SMEM_FLOATS * sizeof(float);

    cudaFuncSetAttribute(fused_gated_ds_kernel,
                         cudaFuncAttributeMaxDynamicSharedMemorySize,
                         (int)smem_bytes);

    const int rows_per_cta = THREADS * RPT;
    const int grid = (Btot + rows_per_cta - 1) / rows_per_cta;
    fused_gated_ds_kernel<<<grid, THREADS, smem_bytes>>>(
        x_cur, W1, b1, W2, b2, Bm, Cm, xt, out, Btot);
}

// round 4
// speedup vs baseline: 1.0919x; 1.0919x over previous
#include <cuda_runtime.h>
#include <cstddef>

// Problem constants (fixed by the dataset)
#define DD 16     // ds_dim
#define NN 32     // number of systems
#define HH 128    // gating hidden width
#define THREADS 384
#define RPT 2     // rows per thread

typedef unsigned long long ull;

// ---- f32x2 packed-math helpers (sm_103a) ----
__device__ __forceinline__ ull pack2(float lo, float hi) {
    ull r; asm("mov.b64 %0, {%1,%2};" : "=l"(r) : "f"(lo), "f"(hi)); return r;
}
__device__ __forceinline__ ull dup2(float v) { return pack2(v, v); }
__device__ __forceinline__ void unpack2(ull v, float& lo, float& hi) {
    asm("mov.b64 {%0,%1}, %2;" : "=f"(lo), "=f"(hi) : "l"(v));
}
__device__ __forceinline__ ull fma2(ull a, ull b, ull c) {
    ull d; asm("fma.rn.f32x2 %0, %1, %2, %3;" : "=l"(d) : "l"(a), "l"(b), "l"(c));
    return d;
}
__device__ __forceinline__ ull add2(ull a, ull b) {
    ull d; asm("add.rn.f32x2 %0, %1, %2;" : "=l"(d) : "l"(a), "l"(b)); return d;
}

// Dynamic smem layout (floats):
//   sW1  [H*D]        W1[j][d] row-major
//   sW2t [H*N]        transposed: sW2t[j*N + n] = W2[n*H + j]
//   sA   [N*D*D]      transposed A: sA[n*256 + d*16 + k] = (B+C)[n][k][d]
//   sb1  [H], sb2 [N], sxt [D]
//   swb  [N*RPT*THREADS]  per-thread softmax weights (conflict-free stride)
#define W_FLOATS (HH*DD + HH*NN + NN*DD*DD + HH + NN + DD)
#define SMEM_FLOATS (W_FLOATS + NN*RPT*THREADS)

__global__ __launch_bounds__(THREADS)
void fused_gated_ds_kernel(
    const float* __restrict__ x_cur,
    const float* __restrict__ W1,
    const float* __restrict__ b1,
    const float* __restrict__ W2,
    const float* __restrict__ b2,
    const float* __restrict__ Bm,
    const float* __restrict__ Cm,
    const float* __restrict__ xt,
    float* __restrict__ out,
    int Btot)
{
    extern __shared__ float smem[];
    float* sW1  = smem;                    // 2048
    float* sW2t = sW1  + HH*DD;            // 4096
    float* sA   = sW2t + HH*NN;            // 8192
    float* sb1  = sA   + NN*DD*DD;         // 128
    float* sb2  = sb1  + HH;               // 32
    float* sxt  = sb2  + NN;               // 16
    float* swb  = smem + W_FLOATS;

    const int tid = threadIdx.x;

    // ---- cooperative stage of all weights into SMEM ----
    for (int i = tid; i < HH*DD; i += THREADS) sW1[i] = W1[i];
    for (int i = tid; i < HH*NN; i += THREADS) {
        int j = i / NN, n = i % NN;
        sW2t[i] = W2[n*HH + j];
    }
    for (int i = tid; i < NN*DD*DD; i += THREADS) {
        int n = i / (DD*DD);
        int r = i % (DD*DD);
        int d = r / DD, k = r % DD;
        int src = n*DD*DD + k*DD + d;      // A[n][k][d] -> sA[n][d][k]
        sA[i] = Bm[src] + Cm[src];
    }
    for (int i = tid; i < HH; i += THREADS) sb1[i] = b1[i];
    if (tid < NN) sb2[tid] = b2[tid];
    if (tid < DD) sxt[tid] = xt[tid];
    __syncthreads();

    const int base = blockIdx.x * (THREADS * RPT);
    const int r0 = base + tid;
    const int r1 = base + THREADS + tid;
    if (r0 >= Btot) return;
    const bool act1 = (r1 < Btot);

    // ---- load x rows, packed (x[2q], x[2q+1]) ----
    ull xp[RPT][8];
    {
        const ulonglong2* xg = reinterpret_cast<const ulonglong2*>(x_cur + (size_t)r0 * DD);
        #pragma unroll
        for (int q = 0; q < 4; q++) { ulonglong2 v = xg[q]; xp[0][2*q] = v.x; xp[0][2*q+1] = v.y; }
    }
    if (act1) {
        const ulonglong2* xg = reinterpret_cast<const ulonglong2*>(x_cur + (size_t)r1 * DD);
        #pragma unroll
        for (int q = 0; q < 4; q++) { ulonglong2 v = xg[q]; xp[1][2*q] = v.x; xp[1][2*q+1] = v.y; }
    } else {
        #pragma unroll
        for (int i = 0; i < 8; i++) xp[1][i] = 0ULL;
    }

    // ---- logits, packed over n: Lp[r][i] covers n = 2i, 2i+1 ----
    ull Lp[RPT][16];
    {
        const ulonglong2* b2p = reinterpret_cast<const ulonglong2*>(sb2);
        #pragma unroll
        for (int q = 0; q < 8; q++) {
            ulonglong2 v = b2p[q];
            Lp[0][2*q]   = v.x; Lp[0][2*q+1] = v.y;
            Lp[1][2*q]   = v.x; Lp[1][2*q+1] = v.y;
        }
    }

    // ---- fused GEMM1 (relu) + GEMM2, streaming over j; weights shared by both rows ----
    #pragma unroll 2
    for (int j = 0; j < HH; j++) {
        const ulonglong2* w1p = reinterpret_cast<const ulonglong2*>(sW1 + j*DD);
        ulonglong2 wA = w1p[0], wB = w1p[1];
        const float bj = sb1[j];
        ull hd[RPT];
        #pragma unroll
        for (int r = 0; r < RPT; r++) {
            ull s0 = fma2(wA.x, xp[r][0], 0ULL);
            ull s1 = fma2(wA.y, xp[r][1], 0ULL);
            s0 = fma2(wB.x, xp[r][2], s0);
            s1 = fma2(wB.y, xp[r][3], s1);
            ulonglong2 wC = w1p[2], wD = w1p[3];
            s0 = fma2(wC.x, xp[r][4], s0);
            s1 = fma2(wC.y, xp[r][5], s1);
            s0 = fma2(wD.x, xp[r][6], s0);
            s1 = fma2(wD.y, xp[r][7], s1);
            ull s = add2(s0, s1);
            float lo, hi; unpack2(s, lo, hi);
            float hj = fmaxf(lo + hi + bj, 0.0f);
            hd[r] = dup2(hj);
        }
        const ulonglong2* w2p = reinterpret_cast<const ulonglong2*>(sW2t + j*NN);
        #pragma unroll
        for (int q = 0; q < 8; q++) {
            ulonglong2 wv = w2p[q];
            #pragma unroll
            for (int r = 0; r < RPT; r++) {
                Lp[r][2*q]   = fma2(wv.x, hd[r], Lp[r][2*q]);
                Lp[r][2*q+1] = fma2(wv.y, hd[r], Lp[r][2*q+1]);
            }
        }
    }

    // ---- softmax per row; stash exp() weights in SMEM (conflict-free per-thread stride) ----
    float inv[RPT];
    #pragma unroll
    for (int r = 0; r < RPT; r++) {
        float ev[NN];
        #pragma unroll
        for (int i = 0; i < 16; i++) unpack2(Lp[r][i], ev[2*i], ev[2*i+1]);
        float m = ev[0];
        #pragma unroll
        for (int n = 1; n < NN; n++) m = fmaxf(m, ev[n]);
        float s = 0.0f;
        #pragma unroll
        for (int n = 0; n < NN; n++) { ev[n] = __expf(ev[n] - m); s += ev[n]; }
        inv[r] = 1.0f / s;
        #pragma unroll
        for (int n = 0; n < NN; n++) swb[(n*RPT + r)*THREADS + tid] = ev[n];
    }

    // ---- diff = x_target - x (scalar; xp dies here) ----
    float diffs[RPT][DD];
    #pragma unroll
    for (int r = 0; r < RPT; r++) {
        #pragma unroll
        for (int q = 0; q < 8; q++) {
            float lo, hi; unpack2(xp[r][q], lo, hi);
            diffs[r][2*q]   = sxt[2*q]   - lo;
            diffs[r][2*q+1] = sxt[2*q+1] - hi;
        }
    }

    // ---- epilogue: out[k] = sum_n w_n * sum_d A[n][d][k] diff[d], packed over k ----
    ull outp[RPT][8];
    #pragma unroll
    for (int r = 0; r < RPT; r++)
        #pragma unroll
        for (int q = 0; q < 8; q++) outp[r][q] = 0ULL;

    #pragma unroll 1
    for (int n = 0; n < NN; n++) {
        const ulonglong2* ap = reinterpret_cast<const ulonglong2*>(sA + n*DD*DD);
        ull pp[RPT][8];
        #pragma unroll
        for (int r = 0; r < RPT; r++)
            #pragma unroll
            for (int q = 0; q < 8; q++) pp[r][q] = 0ULL;

        #pragma unroll
        for (int d = 0; d < DD; d++) {
            ulonglong2 aA = ap[4*d + 0];
            ulonglong2 aB = ap[4*d + 1];
            ulonglong2 aC = ap[4*d + 2];
            ulonglong2 aD = ap[4*d + 3];
            #pragma unroll
            for (int r = 0; r < RPT; r++) {
                const ull ddv = dup2(diffs[r][d]);
                pp[r][0] = fma2(aA.x, ddv, pp[r][0]);
                pp[r][1] = fma2(aA.y, ddv, pp[r][1]);
                pp[r][2] = fma2(aB.x, ddv, pp[r][2]);
                pp[r][3] = fma2(aB.y, ddv, pp[r][3]);
                pp[r][4] = fma2(aC.x, ddv, pp[r][4]);
                pp[r][5] = fma2(aC.y, ddv, pp[r][5]);
                pp[r][6] = fma2(aD.x, ddv, pp[r][6]);
                pp[r][7] = fma2(aD.y, ddv, pp[r][7]);
            }
        }
        #pragma unroll
        for (int r = 0; r < RPT; r++) {
            const ull wd = dup2(swb[(n*RPT + r)*THREADS + tid]);
            #pragma unroll
            for (int q = 0; q < 8; q++)
                outp[r][q] = fma2(wd, pp[r][q], outp[r][q]);
        }
    }

    // ---- store (softmax normalization folded in) ----
    {
        float4* o = reinterpret_cast<float4*>(out + (size_t)r0 * DD);
        #pragma unroll
        for (int q = 0; q < 4; q++) {
            float a, b, c, d;
            unpack2(outp[0][2*q], a, b);
            unpack2(outp[0][2*q+1], c, d);
            o[q] = make_float4(a*inv[0], b*inv[0], c*inv[0], d*inv[0]);
        }
    }
    if (act1) {
        float4* o = reinterpret_cast<float4*>(out + (size_t)r1 * DD);
        #pragma unroll
        for (int q = 0; q < 4; q++) {
            float a, b, c, d;
            unpack2(outp[1][2*q], a, b);
            unpack2(outp[1][2*q+1], c, d);
            o[q] = make_float4(a*inv[1], b*inv[1], c*inv[1], d*inv[1]);
        }
    }
}

extern "C" void kernel_launch(void* const* d_in, const int* in_sizes, int n_in,
                              void* d_out, int out_size)
{
    const float* x_cur = (const float*)d_in[0];
    const float* W1    = (const float*)d_in[1];
    const float* b1    = (const float*)d_in[2];
    const float* W2    = (const float*)d_in[3];
    const float* b2    = (const float*)d_in[4];
    const float* Bm    = (const float*)d_in[5];
    const float* Cm    = (const float*)d_in[6];
    const float* xt    = (const float*)d_in[7];
    float* out = (float*)d_out;

    const int Btot = in_sizes[0] / DD;
    const size_t smem_bytes = (size_t)SMEM_FLOATS * sizeof(float);

    cudaFuncSetAttribute(fused_gated_ds_kernel,
                         cudaFuncAttributeMaxDynamicSharedMemorySize,
                         (int)smem_bytes);

    const int rows_per_cta = THREADS * RPT;
    const int grid = (Btot + rows_per_cta - 1) / rows_per_cta;
    fused_gated_ds_kernel<<<grid, THREADS, smem_bytes>>>(
        x_cur, W1, b1, W2, b2, Bm, Cm, xt, out, Btot);
}